// round 14
// baseline (speedup 1.0000x reference)
#include <cuda_runtime.h>
#include <cuda_bf16.h>
#include <math.h>

// ----------------------------------------------------------------------------
// RARL2 objective via Markov expansion + Parseval, GEMMs on bf16 tensor cores.
//
//   objective = ( 99 * sum_k ||G'_k||_F^2 + || sum_k G'_k ||_F^2 ) / 100,
//   G'_0 = D_F,  G'_k = C_F A_F^{k-1} B_F - (C A^{k-1})[:, :128],  K = 16.
//   (measured: K=8 truncation -> 3.7e-3, K=16 -> 2.6e-5; keep K=16)
//
// Complex GEMM via mma.sync.m16n8k16 bf16 with 2-way split (hi+lo):
//   x*y ~= xh*yh + xh*yl + xl*yh
//   Cre += Ar*Br - Ai*Bi   (negated Ai via sign XOR on bf16x2)
//   Cim += Ar*Bi + Ai*Br
// 256-thread blocks, 8 warps (4m x 2n), warp tile m16n16, block tile 64x32.
// ----------------------------------------------------------------------------

#define NS   256
#define NF   384
#define MM   128
#define PP   128
#define STRIDE 8
#define TSTEPS 2   // K = STRIDE*TSTEPS = 16 Markov parameters

// -------------------- device scratch (static, no allocs) --------------------
__device__ __align__(16) float2 g_Af[NF * NF];
__device__ __align__(16) float2 g_P2[NF * NF];
__device__ __align__(16) float2 g_P4[NF * NF];
__device__ __align__(16) float2 g_P8[NF * NF];
__device__ __align__(16) float2 g_A [NS * NS];
__device__ __align__(16) float2 g_Q2[NS * NS];
__device__ __align__(16) float2 g_Q4[NS * NS];
__device__ __align__(16) float2 g_Q8[NS * NS];
__device__ __align__(16) float2 g_Bf[NF * MM];
__device__ __align__(16) float2 g_VF[2][STRIDE * PP * NF];
__device__ __align__(16) float2 g_VH[2][STRIDE * PP * NS];
__device__ __align__(16) float2 g_G [TSTEPS * STRIDE * PP * MM];
__device__ double2 g_part[128];
__device__ int g_isDouble;

// -------------------- dtype detection ---------------------------------------
__global__ void detect_kernel(const void* probe)
{
    if (threadIdx.x != 0 || blockIdx.x != 0) return;
    const double* pd = (const double*)probe;
    int ok = 1;
    for (int i = 0; i < 32; i++) {
        double v = pd[i];
        double a = fabs(v);
        if (!isfinite(v) || a < 1e-12 || a > 1e6) { ok = 0; break; }
    }
    g_isDouble = ok;
}

__device__ __forceinline__ float ld_val(const void* p, int i)
{
    return g_isDouble ? (float)((const double*)p)[i] : ((const float*)p)[i];
}
__device__ __forceinline__ double ld_vald(const void* p, int i)
{
    return g_isDouble ? ((const double*)p)[i] : (double)((const float*)p)[i];
}

// -------------------- prep: inputs -> fp32 complex scratch -------------------
__global__ void prep_kernel(const void* Cre,  const void* Cim,
                            const void* Are,  const void* Aim,
                            const void* AFre, const void* AFim,
                            const void* BFre, const void* BFim,
                            const void* CFre, const void* CFim)
{
    int i = blockIdx.x * blockDim.x + threadIdx.x;
    if (i < NF * NF) g_Af[i]    = make_float2(ld_val(AFre, i), ld_val(AFim, i));
    if (i < NS * NS) g_A[i]     = make_float2(ld_val(Are,  i), ld_val(Aim,  i));
    if (i < NF * MM) g_Bf[i]    = make_float2(ld_val(BFre, i), ld_val(BFim, i));
    if (i < PP * NF) g_VF[0][i] = make_float2(ld_val(CFre, i), ld_val(CFim, i));
    if (i < PP * NS) g_VH[0][i] = make_float2(ld_val(Cre,  i), ld_val(Cim,  i));
}

// -------------------- bf16 split helpers -------------------------------------
__device__ __forceinline__ unsigned pack2(float v0, float v1)
{
    unsigned r;
    asm("cvt.rn.bf16x2.f32 %0, %1, %2;" : "=r"(r) : "f"(v1), "f"(v0));
    return r;
}
__device__ __forceinline__ void split2(float v0, float v1, unsigned& h, unsigned& l)
{
    h = pack2(v0, v1);
    float h0 = __bfloat162float(__ushort_as_bfloat16((unsigned short)(h & 0xFFFF)));
    float h1 = __bfloat162float(__ushort_as_bfloat16((unsigned short)(h >> 16)));
    l = pack2(v0 - h0, v1 - h1);
}

#define MMAB(d, a, b0, b1)                                                     \
    asm volatile(                                                              \
        "mma.sync.aligned.m16n8k16.row.col.f32.bf16.bf16.f32 "                 \
        "{%0,%1,%2,%3},{%4,%5,%6,%7},{%8,%9},{%0,%1,%2,%3};"                   \
        : "+f"(d[0]), "+f"(d[1]), "+f"(d[2]), "+f"(d[3])                       \
        : "r"(a[0]), "r"(a[1]), "r"(a[2]), "r"(a[3]), "r"(b0), "r"(b1))

// -------------------- multi-segment complex GEMM (bf16 tensor cores) ---------
// Block tile 64x32 complex, 256 threads = 8 warps (4m x 2n); warp tile m16n16.
struct Seg {
    const float2* A;
    const float2* B;
    float2*       C;
    const float2* Sub;
    int lda, ldb, ldc, ldsub, K, gw, blkEnd;
};
struct Seg4 { Seg s[4]; int n; };

#define K2P 17   // padded k2 stride (16 k-pairs + 1)

__global__ void __launch_bounds__(256, 2) cgemm_tc(Seg4 segs)
{
    // segment lookup
    int si = 0;
#pragma unroll
    for (int i = 0; i < 4; i++)
        if (i < segs.n && (int)blockIdx.x >= segs.s[i].blkEnd) si = i + 1;
    const Seg sg = segs.s[si];
    const int blkStart = (si == 0) ? 0 : segs.s[si - 1].blkEnd;
    const int local = blockIdx.x - blkStart;
    const int rowBase = (local / sg.gw) << 6;   // 64-row tiles
    const int colBase = (local % sg.gw) << 5;   // 32-col tiles

    __shared__ unsigned AsRH[64 * K2P], AsRL[64 * K2P];
    __shared__ unsigned AsIH[64 * K2P], AsIL[64 * K2P];
    __shared__ unsigned BsRH[32 * K2P], BsRL[32 * K2P];
    __shared__ unsigned BsIH[32 * K2P], BsIL[32 * K2P];

    const int tid  = threadIdx.x;
    const int lane = tid & 31;
    const int warp = tid >> 5;
    const int warpM = (warp >> 1) << 4;   // 0,16,32,48
    const int warpN = (warp & 1) << 4;    // 0,16
    const int g  = lane >> 2;             // 0..7
    const int t4 = lane & 3;              // 0..3

    float accR[2][4], accI[2][4];
#pragma unroll
    for (int j = 0; j < 2; j++)
#pragma unroll
        for (int r = 0; r < 4; r++) { accR[j][r] = 0.f; accI[j][r] = 0.f; }

    for (int k0 = 0; k0 < sg.K; k0 += 32) {
        __syncthreads();
        // stage + split A: 64 rows x 16 k-pairs (1024 entries, 4 per thread)
#pragma unroll
        for (int l = 0; l < 4; l++) {
            int flat = tid + (l << 8);
            int row = flat >> 4;
            int k2  = flat & 15;
            const float4 v = *(const float4*)(sg.A + (size_t)(rowBase + row) * sg.lda
                                              + (k0 + (k2 << 1)));
            unsigned h, lo;
            int idx = row * K2P + k2;
            split2(v.x, v.z, h, lo); AsRH[idx] = h; AsRL[idx] = lo;
            split2(v.y, v.w, h, lo); AsIH[idx] = h; AsIL[idx] = lo;
        }
        // stage + split B: 32 cols x 16 k-pairs (512 entries, 2 per thread)
#pragma unroll
        for (int l = 0; l < 2; l++) {
            int flat = tid + (l << 8);
            int col = flat & 31;
            int k2  = flat >> 5;
            const float2* bp = sg.B + (size_t)(k0 + (k2 << 1)) * sg.ldb + (colBase + col);
            float2 b0 = bp[0];
            float2 b1 = bp[sg.ldb];
            unsigned h, lo;
            int idx = col * K2P + k2;
            split2(b0.x, b1.x, h, lo); BsRH[idx] = h; BsRL[idx] = lo;
            split2(b0.y, b1.y, h, lo); BsIH[idx] = h; BsIL[idx] = lo;
        }
        __syncthreads();

#pragma unroll
        for (int s = 0; s < 2; s++) {
            const int kb = s << 3;
            const int r0 = (warpM + g) * K2P + kb + t4;
            const int r1 = r0 + 8 * K2P;
            unsigned ArH[4] = { AsRH[r0], AsRH[r1], AsRH[r0 + 4], AsRH[r1 + 4] };
            unsigned ArL[4] = { AsRL[r0], AsRL[r1], AsRL[r0 + 4], AsRL[r1 + 4] };
            unsigned AiH[4] = { AsIH[r0], AsIH[r1], AsIH[r0 + 4], AsIH[r1 + 4] };
            unsigned AiL[4] = { AsIL[r0], AsIL[r1], AsIL[r0 + 4], AsIL[r1 + 4] };
            unsigned NiH[4] = { AiH[0] ^ 0x80008000u, AiH[1] ^ 0x80008000u,
                                AiH[2] ^ 0x80008000u, AiH[3] ^ 0x80008000u };
            unsigned NiL[4] = { AiL[0] ^ 0x80008000u, AiL[1] ^ 0x80008000u,
                                AiL[2] ^ 0x80008000u, AiL[3] ^ 0x80008000u };

            const int c0 = (warpN + g) * K2P + kb + t4;
            const int c1 = (warpN + 8 + g) * K2P + kb + t4;
            unsigned B0rH0 = BsRH[c0], B0rH1 = BsRH[c0 + 4];
            unsigned B0rL0 = BsRL[c0], B0rL1 = BsRL[c0 + 4];
            unsigned B0iH0 = BsIH[c0], B0iH1 = BsIH[c0 + 4];
            unsigned B0iL0 = BsIL[c0], B0iL1 = BsIL[c0 + 4];
            unsigned B1rH0 = BsRH[c1], B1rH1 = BsRH[c1 + 4];
            unsigned B1rL0 = BsRL[c1], B1rL1 = BsRL[c1 + 4];
            unsigned B1iH0 = BsIH[c1], B1iH1 = BsIH[c1 + 4];
            unsigned B1iL0 = BsIL[c1], B1iL1 = BsIL[c1 + 4];

            // 24 MMAs, same-acc reuse distance 4
            // term 0: ArH * BH
            MMAB(accR[0], ArH, B0rH0, B0rH1);
            MMAB(accI[0], ArH, B0iH0, B0iH1);
            MMAB(accR[1], ArH, B1rH0, B1rH1);
            MMAB(accI[1], ArH, B1iH0, B1iH1);
            // term 1: ArH * BL
            MMAB(accR[0], ArH, B0rL0, B0rL1);
            MMAB(accI[0], ArH, B0iL0, B0iL1);
            MMAB(accR[1], ArH, B1rL0, B1rL1);
            MMAB(accI[1], ArH, B1iL0, B1iL1);
            // term 2: ArL * BH
            MMAB(accR[0], ArL, B0rH0, B0rH1);
            MMAB(accI[0], ArL, B0iH0, B0iH1);
            MMAB(accR[1], ArL, B1rH0, B1rH1);
            MMAB(accI[1], ArL, B1iH0, B1iH1);
            // term 3: (-Ai)H*BiH / AiH*BrH
            MMAB(accR[0], NiH, B0iH0, B0iH1);
            MMAB(accI[0], AiH, B0rH0, B0rH1);
            MMAB(accR[1], NiH, B1iH0, B1iH1);
            MMAB(accI[1], AiH, B1rH0, B1rH1);
            // term 4: (-Ai)H*BiL / AiH*BrL
            MMAB(accR[0], NiH, B0iL0, B0iL1);
            MMAB(accI[0], AiH, B0rL0, B0rL1);
            MMAB(accR[1], NiH, B1iL0, B1iL1);
            MMAB(accI[1], AiH, B1rL0, B1rL1);
            // term 5: (-Ai)L*BiH / AiL*BrH
            MMAB(accR[0], NiL, B0iH0, B0iH1);
            MMAB(accI[0], AiL, B0rH0, B0rH1);
            MMAB(accR[1], NiL, B1iH0, B1iH1);
            MMAB(accI[1], AiL, B1rH0, B1rH1);
        }
    }

    // epilogue: c layout: row = g + 8*(r>>1), col = 2*t4 + (r&1)
#pragma unroll
    for (int jn = 0; jn < 2; jn++) {
#pragma unroll
        for (int r = 0; r < 4; r++) {
            int row = rowBase + warpM + g + ((r >> 1) << 3);
            int col = colBase + warpN + (jn << 3) + (t4 << 1) + (r & 1);
            float2 v = make_float2(accR[jn][r], accI[jn][r]);
            if (sg.Sub != nullptr) {
                float2 s2 = sg.Sub[(size_t)row * sg.ldsub + col];
                v.x -= s2.x;
                v.y -= s2.y;
            }
            sg.C[(size_t)row * sg.ldc + col] = v;
        }
    }
}

// -------------------- reduction ---------------------------------------------
__global__ void reduceA_kernel(const void* __restrict__ DFre,
                               const void* __restrict__ DFim)
{
    int e = blockIdx.x * 128 + threadIdx.x;   // (p, m)
    int p = e >> 7;
    int m = e & 127;

    double sre = ld_vald(DFre, e);
    double sim = ld_vald(DFim, e);
    double nrm = sre * sre + sim * sim;

#pragma unroll 1
    for (int t = 0; t < TSTEPS; t++) {
        const float2* Gt = g_G + (size_t)t * (STRIDE * PP * MM);
#pragma unroll
        for (int r = 0; r < STRIDE; r++) {
            float2 g = Gt[(size_t)(r * PP + p) * MM + m];
            sre += (double)g.x;
            sim += (double)g.y;
            nrm += (double)g.x * (double)g.x + (double)g.y * (double)g.y;
        }
    }
    double sq = sre * sre + sim * sim;

    __shared__ double shn[128];
    __shared__ double shs[128];
    shn[threadIdx.x] = nrm;
    shs[threadIdx.x] = sq;
    __syncthreads();
    for (int o = 64; o > 0; o >>= 1) {
        if (threadIdx.x < o) {
            shn[threadIdx.x] += shn[threadIdx.x + o];
            shs[threadIdx.x] += shs[threadIdx.x + o];
        }
        __syncthreads();
    }
    if (threadIdx.x == 0) g_part[blockIdx.x] = make_double2(shn[0], shs[0]);
}

__global__ void reduceB_kernel(void* __restrict__ out)
{
    __shared__ double shn[128];
    __shared__ double shs[128];
    double2 v = g_part[threadIdx.x];
    shn[threadIdx.x] = v.x;
    shs[threadIdx.x] = v.y;
    __syncthreads();
    for (int o = 64; o > 0; o >>= 1) {
        if (threadIdx.x < o) {
            shn[threadIdx.x] += shn[threadIdx.x + o];
            shs[threadIdx.x] += shs[threadIdx.x + o];
        }
        __syncthreads();
    }
    if (threadIdx.x == 0) {
        double res = (99.0 * shn[0] + shs[0]) / 100.0;
        if (g_isDouble) ((double*)out)[0] = res;
        else            ((float*)out)[0]  = (float)res;
    }
}

// -------------------- host helpers ------------------------------------------
static inline Seg mkseg(const float2* A, int lda, const float2* B, int ldb,
                        float2* C, int ldc, int K, int rows, int cols,
                        const float2* Sub = nullptr, int ldsub = 0)
{
    Seg s;
    s.A = A; s.B = B; s.C = C; s.Sub = Sub;
    s.lda = lda; s.ldb = ldb; s.ldc = ldc; s.ldsub = ldsub;
    s.K = K; s.gw = cols / 32; s.blkEnd = (rows / 64) * (cols / 32);
    return s;
}

static inline void launch_segs(Seg* s, int n)
{
    Seg4 packed;
    int cum = 0;
    for (int i = 0; i < n; i++) {
        cum += s[i].blkEnd;           // blkEnd currently holds block count
        packed.s[i] = s[i];
        packed.s[i].blkEnd = cum;
    }
    for (int i = n; i < 4; i++) packed.s[i] = packed.s[n - 1];
    packed.n = n;
    cgemm_tc<<<cum, 256>>>(packed);
}

// -------------------- host orchestration ------------------------------------
extern "C" void kernel_launch(void* const* d_in, const int* in_sizes, int n_in,
                              void* d_out, int out_size)
{
    (void)out_size;

    // resolve input slots by element count:
    // C = 32768, A = 65536, A_F = 147456, B_F/C_F = 49152, D_F = 16384
    int iC[2] = {0, 0}, iA[2] = {0, 0}, iAF[2] = {0, 0};
    int iBC[4] = {0, 0, 0, 0}, iDF[2] = {0, 0};
    int nC = 0, nA = 0, nAF = 0, nBC = 0, nDF = 0;
    for (int i = 0; i < n_in && i < 12; i++) {
        switch (in_sizes[i]) {
            case 32768:  if (nC  < 2) iC[nC++]   = i; break;
            case 65536:  if (nA  < 2) iA[nA++]   = i; break;
            case 147456: if (nAF < 2) iAF[nAF++] = i; break;
            case 49152:  if (nBC < 4) iBC[nBC++] = i; break;
            case 16384:  if (nDF < 2) iDF[nDF++] = i; break;
            default: break;
        }
    }
    const bool imagFirst = (n_in > 0 && in_sizes[0] == 147456);
    const int re = imagFirst ? 1 : 0;
    const int im = imagFirst ? 0 : 1;

    const void* Cre  = d_in[iC[re]];
    const void* Cim  = d_in[iC[im]];
    const void* Are  = d_in[iA[re]];
    const void* Aim  = d_in[iA[im]];
    const void* AFre = d_in[iAF[re]];
    const void* AFim = d_in[iAF[im]];
    const void* BFre = d_in[iBC[0 + re]];
    const void* BFim = d_in[iBC[0 + im]];
    const void* CFre = d_in[iBC[2 + re]];
    const void* CFim = d_in[iBC[2 + im]];
    const void* DFre = d_in[iDF[re]];
    const void* DFim = d_in[iDF[im]];

    float2 *pAf, *pP2, *pP4, *pP8, *pA, *pQ2, *pQ4, *pQ8, *pBf, *pVF, *pVH, *pG;
    cudaGetSymbolAddress((void**)&pAf, g_Af);
    cudaGetSymbolAddress((void**)&pP2, g_P2);
    cudaGetSymbolAddress((void**)&pP4, g_P4);
    cudaGetSymbolAddress((void**)&pP8, g_P8);
    cudaGetSymbolAddress((void**)&pA,  g_A);
    cudaGetSymbolAddress((void**)&pQ2, g_Q2);
    cudaGetSymbolAddress((void**)&pQ4, g_Q4);
    cudaGetSymbolAddress((void**)&pQ8, g_Q8);
    cudaGetSymbolAddress((void**)&pBf, g_Bf);
    cudaGetSymbolAddress((void**)&pVF, g_VF);
    cudaGetSymbolAddress((void**)&pVH, g_VH);
    cudaGetSymbolAddress((void**)&pG,  g_G);

    float2* VF0 = pVF;
    float2* VF1 = pVF + STRIDE * PP * NF;
    float2* VH0 = pVH;
    float2* VH1 = pVH + STRIDE * PP * NS;

    // 0) detect dtype; 1) convert inputs -> fp32 complex
    detect_kernel<<<1, 1>>>(AFre);
    prep_kernel<<<(NF * NF + 255) / 256, 256>>>(Cre, Cim, Are, Aim, AFre, AFim,
                                                BFre, BFim, CFre, CFim);

    // L1: P2 = Af^2, Q2 = A^2, VF rows[128:256) = VF[0:128)*Af, VH likewise
    {
        Seg s[4] = {
            mkseg(pAf, NF, pAf, NF, pP2, NF, NF, NF, NF),
            mkseg(pA,  NS, pA,  NS, pQ2, NS, NS, NS, NS),
            mkseg(VF0, NF, pAf, NF, VF0 + 128 * NF, NF, NF, 128, NF),
            mkseg(VH0, NS, pA,  NS, VH0 + 128 * NS, NS, NS, 128, NS),
        };
        launch_segs(s, 4);
    }
    // L2: P4 = P2^2, Q4 = Q2^2, VF rows[256:512) = VF[0:256)*P2, VH likewise
    {
        Seg s[4] = {
            mkseg(pP2, NF, pP2, NF, pP4, NF, NF, NF, NF),
            mkseg(pQ2, NS, pQ2, NS, pQ4, NS, NS, NS, NS),
            mkseg(VF0, NF, pP2, NF, VF0 + 256 * NF, NF, NF, 256, NF),
            mkseg(VH0, NS, pQ2, NS, VH0 + 256 * NS, NS, NS, 256, NS),
        };
        launch_segs(s, 4);
    }
    // L3: P8 = P4^2, Q8 = Q4^2, VF rows[512:1024) = VF[0:512)*P4, VH likewise
    {
        Seg s[4] = {
            mkseg(pP4, NF, pP4, NF, pP8, NF, NF, NF, NF),
            mkseg(pQ4, NS, pQ4, NS, pQ8, NS, NS, NS, NS),
            mkseg(VF0, NF, pP4, NF, VF0 + 512 * NF, NF, NF, 512, NF),
            mkseg(VH0, NS, pQ4, NS, VH0 + 512 * NS, NS, NS, 512, NS),
        };
        launch_segs(s, 4);
    }
    // L4: G_0 = VF0*Bf - VH0[:, :128];  VF1 = VF0*P8;  VH1 = VH0*Q8
    {
        Seg s[3] = {
            mkseg(VF0, NF, pBf, MM, pG, MM, NF, STRIDE * PP, MM, VH0, NS),
            mkseg(VF0, NF, pP8, NF, VF1, NF, NF, STRIDE * PP, NF),
            mkseg(VH0, NS, pQ8, NS, VH1, NS, NS, STRIDE * PP, NS),
        };
        launch_segs(s, 3);
    }
    // L5: G_1 = VF1*Bf - VH1[:, :128]
    {
        Seg s[1] = {
            mkseg(VF1, NF, pBf, MM, pG + STRIDE * PP * MM, MM, NF,
                  STRIDE * PP, MM, VH1, NS),
        };
        launch_segs(s, 1);
    }

    // Parseval reduction (fp64, deterministic)
    reduceA_kernel<<<128, 128>>>(DFre, DFim);
    reduceB_kernel<<<1, 128>>>(d_out);
}

// round 17
// speedup vs baseline: 1.1379x; 1.1379x over previous
#include <cuda_runtime.h>
#include <cuda_bf16.h>
#include <stdint.h>
#include <math.h>

// ----------------------------------------------------------------------------
// RARL2 objective via Markov expansion + Parseval, GEMMs on bf16 tensor cores.
//
//   objective = ( 99 * sum_k ||G'_k||_F^2 + || sum_k G'_k ||_F^2 ) / 100,
//   G'_0 = D_F,  G'_k = C_F A_F^{k-1} B_F - (C A^{k-1})[:, :128],  K = 16.
//
// B-side folding: G_{r+9} = (C_F A_F^r) * (A_F^8 B_F), so k=9..16 uses
// B8 = A_F^8 B_F (skinny) instead of propagating the 1024-row V chains.
// H side: H1 = VH * (A^8 E), with A^8 E = Q4 * Q4[:, :128].
// Total complex-MACs: 517M (was 729M); no P8/Q8.
//
// Complex GEMM via mma.sync.m16n8k16 bf16 with 2-way split (hi+lo):
//   x*y ~= xh*yh + xh*yl + xl*yh
// 256-thread blocks, 8 warps (4m x 2n), warp tile m16n16, block tile 64x32.
// ----------------------------------------------------------------------------

#define NS   256
#define NF   384
#define MM   128
#define PP   128
#define STRIDE 8
#define TSTEPS 2   // K = 16 Markov parameters

// -------------------- device scratch (static, no allocs) --------------------
__device__ __align__(16) float2 g_Af[NF * NF];
__device__ __align__(16) float2 g_P2[NF * NF];
__device__ __align__(16) float2 g_P4[NF * NF];
__device__ __align__(16) float2 g_A [NS * NS];
__device__ __align__(16) float2 g_Q2[NS * NS];
__device__ __align__(16) float2 g_Q4[NS * NS];
__device__ __align__(16) float2 g_Bf[NF * MM];
__device__ __align__(16) float2 g_B4[NF * MM];
__device__ __align__(16) float2 g_B8[NF * MM];
__device__ __align__(16) float2 g_Q8E[NS * MM];
__device__ __align__(16) float2 g_H1[STRIDE * PP * MM];
__device__ __align__(16) float2 g_VF[STRIDE * PP * NF];
__device__ __align__(16) float2 g_VH[STRIDE * PP * NS];
__device__ __align__(16) float2 g_G [TSTEPS * STRIDE * PP * MM];
__device__ double2 g_part[128];
__device__ int g_isDouble;

// -------------------- dtype detection ---------------------------------------
__global__ void detect_kernel(const void* probe)
{
    if (threadIdx.x != 0 || blockIdx.x != 0) return;
    const double* pd = (const double*)probe;
    int ok = 1;
    for (int i = 0; i < 32; i++) {
        double v = pd[i];
        double a = fabs(v);
        if (!isfinite(v) || a < 1e-12 || a > 1e6) { ok = 0; break; }
    }
    g_isDouble = ok;
}

__device__ __forceinline__ float ld_val(const void* p, int i)
{
    return g_isDouble ? (float)((const double*)p)[i] : ((const float*)p)[i];
}
__device__ __forceinline__ double ld_vald(const void* p, int i)
{
    return g_isDouble ? ((const double*)p)[i] : (double)((const float*)p)[i];
}

// -------------------- prep: inputs -> fp32 complex scratch -------------------
__global__ void prep_kernel(const void* Cre,  const void* Cim,
                            const void* Are,  const void* Aim,
                            const void* AFre, const void* AFim,
                            const void* BFre, const void* BFim,
                            const void* CFre, const void* CFim)
{
    int i = blockIdx.x * blockDim.x + threadIdx.x;
    if (i < NF * NF) g_Af[i] = make_float2(ld_val(AFre, i), ld_val(AFim, i));
    if (i < NS * NS) g_A[i]  = make_float2(ld_val(Are,  i), ld_val(Aim,  i));
    if (i < NF * MM) g_Bf[i] = make_float2(ld_val(BFre, i), ld_val(BFim, i));
    if (i < PP * NF) g_VF[i] = make_float2(ld_val(CFre, i), ld_val(CFim, i));
    if (i < PP * NS) g_VH[i] = make_float2(ld_val(Cre,  i), ld_val(Cim,  i));
}

// -------------------- bf16 split helpers -------------------------------------
__device__ __forceinline__ unsigned pack2(float v0, float v1)
{
    unsigned r;
    asm("cvt.rn.bf16x2.f32 %0, %1, %2;" : "=r"(r) : "f"(v1), "f"(v0));
    return r;
}
__device__ __forceinline__ void split2(float v0, float v1, unsigned& h, unsigned& l)
{
    h = pack2(v0, v1);
    float h0 = __bfloat162float(__ushort_as_bfloat16((unsigned short)(h & 0xFFFF)));
    float h1 = __bfloat162float(__ushort_as_bfloat16((unsigned short)(h >> 16)));
    l = pack2(v0 - h0, v1 - h1);
}

#define MMAB(d, a, b0, b1)                                                     \
    asm volatile(                                                              \
        "mma.sync.aligned.m16n8k16.row.col.f32.bf16.bf16.f32 "                 \
        "{%0,%1,%2,%3},{%4,%5,%6,%7},{%8,%9},{%0,%1,%2,%3};"                   \
        : "+f"(d[0]), "+f"(d[1]), "+f"(d[2]), "+f"(d[3])                       \
        : "r"(a[0]), "r"(a[1]), "r"(a[2]), "r"(a[3]), "r"(b0), "r"(b1))

// -------------------- multi-segment complex GEMM (bf16 tensor cores) ---------
// Block tile 64x32 complex, 256 threads = 8 warps (4m x 2n); warp tile m16n16.
struct Seg {
    const float2* A;
    const float2* B;
    float2*       C;
    const float2* Sub;
    int lda, ldb, ldc, ldsub, K, gw, blkEnd;
};
struct Seg4 { Seg s[4]; int n; };

#define K2P 17   // padded k2 stride (16 k-pairs + 1)

__global__ void __launch_bounds__(256, 2) cgemm_tc(Seg4 segs)
{
    // segment lookup
    int si = 0;
#pragma unroll
    for (int i = 0; i < 4; i++)
        if (i < segs.n && (int)blockIdx.x >= segs.s[i].blkEnd) si = i + 1;
    const Seg sg = segs.s[si];
    const int blkStart = (si == 0) ? 0 : segs.s[si - 1].blkEnd;
    const int local = blockIdx.x - blkStart;
    const int rowBase = (local / sg.gw) << 6;   // 64-row tiles
    const int colBase = (local % sg.gw) << 5;   // 32-col tiles

    __shared__ unsigned AsRH[64 * K2P], AsRL[64 * K2P];
    __shared__ unsigned AsIH[64 * K2P], AsIL[64 * K2P];
    __shared__ unsigned BsRH[32 * K2P], BsRL[32 * K2P];
    __shared__ unsigned BsIH[32 * K2P], BsIL[32 * K2P];

    const int tid  = threadIdx.x;
    const int lane = tid & 31;
    const int warp = tid >> 5;
    const int warpM = (warp >> 1) << 4;   // 0,16,32,48
    const int warpN = (warp & 1) << 4;    // 0,16
    const int g  = lane >> 2;             // 0..7
    const int t4 = lane & 3;              // 0..3

    float accR[2][4], accI[2][4];
#pragma unroll
    for (int j = 0; j < 2; j++)
#pragma unroll
        for (int r = 0; r < 4; r++) { accR[j][r] = 0.f; accI[j][r] = 0.f; }

    for (int k0 = 0; k0 < sg.K; k0 += 32) {
        __syncthreads();
        // stage + split A: 64 rows x 16 k-pairs (1024 entries, 4 per thread)
#pragma unroll
        for (int l = 0; l < 4; l++) {
            int flat = tid + (l << 8);
            int row = flat >> 4;
            int k2  = flat & 15;
            const float4 v = *(const float4*)(sg.A + (size_t)(rowBase + row) * sg.lda
                                              + (k0 + (k2 << 1)));
            unsigned h, lo;
            int idx = row * K2P + k2;
            split2(v.x, v.z, h, lo); AsRH[idx] = h; AsRL[idx] = lo;
            split2(v.y, v.w, h, lo); AsIH[idx] = h; AsIL[idx] = lo;
        }
        // stage + split B: 32 cols x 16 k-pairs (512 entries, 2 per thread)
#pragma unroll
        for (int l = 0; l < 2; l++) {
            int flat = tid + (l << 8);
            int col = flat & 31;
            int k2  = flat >> 5;
            const float2* bp = sg.B + (size_t)(k0 + (k2 << 1)) * sg.ldb + (colBase + col);
            float2 b0 = bp[0];
            float2 b1 = bp[sg.ldb];
            unsigned h, lo;
            int idx = col * K2P + k2;
            split2(b0.x, b1.x, h, lo); BsRH[idx] = h; BsRL[idx] = lo;
            split2(b0.y, b1.y, h, lo); BsIH[idx] = h; BsIL[idx] = lo;
        }
        __syncthreads();

#pragma unroll
        for (int s = 0; s < 2; s++) {
            const int kb = s << 3;
            const int r0 = (warpM + g) * K2P + kb + t4;
            const int r1 = r0 + 8 * K2P;
            unsigned ArH[4] = { AsRH[r0], AsRH[r1], AsRH[r0 + 4], AsRH[r1 + 4] };
            unsigned ArL[4] = { AsRL[r0], AsRL[r1], AsRL[r0 + 4], AsRL[r1 + 4] };
            unsigned AiH[4] = { AsIH[r0], AsIH[r1], AsIH[r0 + 4], AsIH[r1 + 4] };
            unsigned AiL[4] = { AsIL[r0], AsIL[r1], AsIL[r0 + 4], AsIL[r1 + 4] };
            unsigned NiH[4] = { AiH[0] ^ 0x80008000u, AiH[1] ^ 0x80008000u,
                                AiH[2] ^ 0x80008000u, AiH[3] ^ 0x80008000u };
            unsigned NiL[4] = { AiL[0] ^ 0x80008000u, AiL[1] ^ 0x80008000u,
                                AiL[2] ^ 0x80008000u, AiL[3] ^ 0x80008000u };

            const int c0 = (warpN + g) * K2P + kb + t4;
            const int c1 = (warpN + 8 + g) * K2P + kb + t4;
            unsigned B0rH0 = BsRH[c0], B0rH1 = BsRH[c0 + 4];
            unsigned B0rL0 = BsRL[c0], B0rL1 = BsRL[c0 + 4];
            unsigned B0iH0 = BsIH[c0], B0iH1 = BsIH[c0 + 4];
            unsigned B0iL0 = BsIL[c0], B0iL1 = BsIL[c0 + 4];
            unsigned B1rH0 = BsRH[c1], B1rH1 = BsRH[c1 + 4];
            unsigned B1rL0 = BsRL[c1], B1rL1 = BsRL[c1 + 4];
            unsigned B1iH0 = BsIH[c1], B1iH1 = BsIH[c1 + 4];
            unsigned B1iL0 = BsIL[c1], B1iL1 = BsIL[c1 + 4];

            // 24 MMAs, same-acc reuse distance 4
            // term 0: ArH * BH
            MMAB(accR[0], ArH, B0rH0, B0rH1);
            MMAB(accI[0], ArH, B0iH0, B0iH1);
            MMAB(accR[1], ArH, B1rH0, B1rH1);
            MMAB(accI[1], ArH, B1iH0, B1iH1);
            // term 1: ArH * BL
            MMAB(accR[0], ArH, B0rL0, B0rL1);
            MMAB(accI[0], ArH, B0iL0, B0iL1);
            MMAB(accR[1], ArH, B1rL0, B1rL1);
            MMAB(accI[1], ArH, B1iL0, B1iL1);
            // term 2: ArL * BH
            MMAB(accR[0], ArL, B0rH0, B0rH1);
            MMAB(accI[0], ArL, B0iH0, B0iH1);
            MMAB(accR[1], ArL, B1rH0, B1rH1);
            MMAB(accI[1], ArL, B1iH0, B1iH1);
            // term 3: (-Ai)H*BiH / AiH*BrH
            MMAB(accR[0], NiH, B0iH0, B0iH1);
            MMAB(accI[0], AiH, B0rH0, B0rH1);
            MMAB(accR[1], NiH, B1iH0, B1iH1);
            MMAB(accI[1], AiH, B1rH0, B1rH1);
            // term 4: (-Ai)H*BiL / AiH*BrL
            MMAB(accR[0], NiH, B0iL0, B0iL1);
            MMAB(accI[0], AiH, B0rL0, B0rL1);
            MMAB(accR[1], NiH, B1iL0, B1iL1);
            MMAB(accI[1], AiH, B1rL0, B1rL1);
            // term 5: (-Ai)L*BiH / AiL*BrH
            MMAB(accR[0], NiL, B0iH0, B0iH1);
            MMAB(accI[0], AiL, B0rH0, B0rH1);
            MMAB(accR[1], NiL, B1iH0, B1iH1);
            MMAB(accI[1], AiL, B1rH0, B1rH1);
        }
    }

    // epilogue: c layout: row = g + 8*(r>>1), col = 2*t4 + (r&1)
#pragma unroll
    for (int jn = 0; jn < 2; jn++) {
#pragma unroll
        for (int r = 0; r < 4; r++) {
            int row = rowBase + warpM + g + ((r >> 1) << 3);
            int col = colBase + warpN + (jn << 3) + (t4 << 1) + (r & 1);
            float2 v = make_float2(accR[jn][r], accI[jn][r]);
            if (sg.Sub != nullptr) {
                float2 s2 = sg.Sub[(size_t)row * sg.ldsub + col];
                v.x -= s2.x;
                v.y -= s2.y;
            }
            sg.C[(size_t)row * sg.ldc + col] = v;
        }
    }
}

// -------------------- reduction ---------------------------------------------
__global__ void reduceA_kernel(const void* __restrict__ DFre,
                               const void* __restrict__ DFim)
{
    int e = blockIdx.x * 128 + threadIdx.x;   // (p, m)
    int p = e >> 7;
    int m = e & 127;

    double sre = ld_vald(DFre, e);
    double sim = ld_vald(DFim, e);
    double nrm = sre * sre + sim * sim;

#pragma unroll 1
    for (int t = 0; t < TSTEPS; t++) {
        const float2* Gt = g_G + (size_t)t * (STRIDE * PP * MM);
#pragma unroll
        for (int r = 0; r < STRIDE; r++) {
            float2 g = Gt[(size_t)(r * PP + p) * MM + m];
            sre += (double)g.x;
            sim += (double)g.y;
            nrm += (double)g.x * (double)g.x + (double)g.y * (double)g.y;
        }
    }
    double sq = sre * sre + sim * sim;

    __shared__ double shn[128];
    __shared__ double shs[128];
    shn[threadIdx.x] = nrm;
    shs[threadIdx.x] = sq;
    __syncthreads();
    for (int o = 64; o > 0; o >>= 1) {
        if (threadIdx.x < o) {
            shn[threadIdx.x] += shn[threadIdx.x + o];
            shs[threadIdx.x] += shs[threadIdx.x + o];
        }
        __syncthreads();
    }
    if (threadIdx.x == 0) g_part[blockIdx.x] = make_double2(shn[0], shs[0]);
}

__global__ void reduceB_kernel(void* __restrict__ out)
{
    __shared__ double shn[128];
    __shared__ double shs[128];
    double2 v = g_part[threadIdx.x];
    shn[threadIdx.x] = v.x;
    shs[threadIdx.x] = v.y;
    __syncthreads();
    for (int o = 64; o > 0; o >>= 1) {
        if (threadIdx.x < o) {
            shn[threadIdx.x] += shn[threadIdx.x + o];
            shs[threadIdx.x] += shs[threadIdx.x + o];
        }
        __syncthreads();
    }
    if (threadIdx.x == 0) {
        double res = (99.0 * shn[0] + shs[0]) / 100.0;
        if (g_isDouble) ((double*)out)[0] = res;
        else            ((float*)out)[0]  = (float)res;
    }
}

// -------------------- host helpers ------------------------------------------
static inline Seg mkseg(const float2* A, int lda, const float2* B, int ldb,
                        float2* C, int ldc, int K, int rows, int cols,
                        const float2* Sub = nullptr, int ldsub = 0)
{
    Seg s;
    s.A = A; s.B = B; s.C = C; s.Sub = Sub;
    s.lda = lda; s.ldb = ldb; s.ldc = ldc; s.ldsub = ldsub;
    s.K = K; s.gw = cols / 32; s.blkEnd = (rows / 64) * (cols / 32);
    return s;
}

static inline void launch_segs(Seg* s, int n)
{
    Seg4 packed;
    int cum = 0;
    for (int i = 0; i < n; i++) {
        cum += s[i].blkEnd;           // blkEnd currently holds block count
        packed.s[i] = s[i];
        packed.s[i].blkEnd = cum;
    }
    for (int i = n; i < 4; i++) packed.s[i] = packed.s[n - 1];
    packed.n = n;
    cgemm_tc<<<cum, 256>>>(packed);
}

// -------------------- host orchestration ------------------------------------
extern "C" void kernel_launch(void* const* d_in, const int* in_sizes, int n_in,
                              void* d_out, int out_size)
{
    (void)out_size;

    // resolve input slots by element count:
    // C = 32768, A = 65536, A_F = 147456, B_F/C_F = 49152, D_F = 16384
    int iC[2] = {0, 0}, iA[2] = {0, 0}, iAF[2] = {0, 0};
    int iBC[4] = {0, 0, 0, 0}, iDF[2] = {0, 0};
    int nC = 0, nA = 0, nAF = 0, nBC = 0, nDF = 0;
    for (int i = 0; i < n_in && i < 12; i++) {
        switch (in_sizes[i]) {
            case 32768:  if (nC  < 2) iC[nC++]   = i; break;
            case 65536:  if (nA  < 2) iA[nA++]   = i; break;
            case 147456: if (nAF < 2) iAF[nAF++] = i; break;
            case 49152:  if (nBC < 4) iBC[nBC++] = i; break;
            case 16384:  if (nDF < 2) iDF[nDF++] = i; break;
            default: break;
        }
    }
    const bool imagFirst = (n_in > 0 && in_sizes[0] == 147456);
    const int re = imagFirst ? 1 : 0;
    const int im = imagFirst ? 0 : 1;

    const void* Cre  = d_in[iC[re]];
    const void* Cim  = d_in[iC[im]];
    const void* Are  = d_in[iA[re]];
    const void* Aim  = d_in[iA[im]];
    const void* AFre = d_in[iAF[re]];
    const void* AFim = d_in[iAF[im]];
    const void* BFre = d_in[iBC[0 + re]];
    const void* BFim = d_in[iBC[0 + im]];
    const void* CFre = d_in[iBC[2 + re]];
    const void* CFim = d_in[iBC[2 + im]];
    const void* DFre = d_in[iDF[re]];
    const void* DFim = d_in[iDF[im]];

    float2 *pAf, *pP2, *pP4, *pA, *pQ2, *pQ4, *pBf, *pB4, *pB8, *pQ8E, *pH1,
           *pVF, *pVH, *pG;
    cudaGetSymbolAddress((void**)&pAf,  g_Af);
    cudaGetSymbolAddress((void**)&pP2,  g_P2);
    cudaGetSymbolAddress((void**)&pP4,  g_P4);
    cudaGetSymbolAddress((void**)&pA,   g_A);
    cudaGetSymbolAddress((void**)&pQ2,  g_Q2);
    cudaGetSymbolAddress((void**)&pQ4,  g_Q4);
    cudaGetSymbolAddress((void**)&pBf,  g_Bf);
    cudaGetSymbolAddress((void**)&pB4,  g_B4);
    cudaGetSymbolAddress((void**)&pB8,  g_B8);
    cudaGetSymbolAddress((void**)&pQ8E, g_Q8E);
    cudaGetSymbolAddress((void**)&pH1,  g_H1);
    cudaGetSymbolAddress((void**)&pVF,  g_VF);
    cudaGetSymbolAddress((void**)&pVH,  g_VH);
    cudaGetSymbolAddress((void**)&pG,   g_G);

    // 0) detect dtype; 1) convert inputs -> fp32 complex
    detect_kernel<<<1, 1>>>(AFre);
    prep_kernel<<<(NF * NF + 255) / 256, 256>>>(Cre, Cim, Are, Aim, AFre, AFim,
                                                BFre, BFim, CFre, CFim);

    // L1: P2 = Af^2, Q2 = A^2, VF rows[128:256) = VF[0:128)*Af, VH likewise
    {
        Seg s[4] = {
            mkseg(pAf, NF, pAf, NF, pP2, NF, NF, NF, NF),
            mkseg(pA,  NS, pA,  NS, pQ2, NS, NS, NS, NS),
            mkseg(pVF, NF, pAf, NF, pVF + 128 * NF, NF, NF, 128, NF),
            mkseg(pVH, NS, pA,  NS, pVH + 128 * NS, NS, NS, 128, NS),
        };
        launch_segs(s, 4);
    }
    // L2: P4 = P2^2, Q4 = Q2^2, VF rows[256:512) = VF[0:256)*P2, VH likewise
    {
        Seg s[4] = {
            mkseg(pP2, NF, pP2, NF, pP4, NF, NF, NF, NF),
            mkseg(pQ2, NS, pQ2, NS, pQ4, NS, NS, NS, NS),
            mkseg(pVF, NF, pP2, NF, pVF + 256 * NF, NF, NF, 256, NF),
            mkseg(pVH, NS, pQ2, NS, pVH + 256 * NS, NS, NS, 256, NS),
        };
        launch_segs(s, 4);
    }
    // L3: VF rows[512:1024) = VF[0:512)*P4; VH likewise;
    //     B4 = P4*Bf (384x128); Q8E = Q4*Q4[:, :128] (256x128)
    {
        Seg s[4] = {
            mkseg(pVF, NF, pP4, NF, pVF + 512 * NF, NF, NF, 512, NF),
            mkseg(pVH, NS, pQ4, NS, pVH + 512 * NS, NS, NS, 512, NS),
            mkseg(pP4, NF, pBf, MM, pB4, MM, NF, NF, MM),
            mkseg(pQ4, NS, pQ4, NS, pQ8E, MM, NS, NS, MM),
        };
        launch_segs(s, 4);
    }
    // L4: B8 = P4*B4 (384x128); G_0 = VF*Bf - VH[:, :128]; H1 = VH*Q8E
    {
        Seg s[3] = {
            mkseg(pP4, NF, pB4, MM, pB8, MM, NF, NF, MM),
            mkseg(pVF, NF, pBf, MM, pG, MM, NF, STRIDE * PP, MM, pVH, NS),
            mkseg(pVH, NS, pQ8E, MM, pH1, MM, NS, STRIDE * PP, MM),
        };
        launch_segs(s, 3);
    }
    // L5: G_1 = VF*B8 - H1
    {
        Seg s[1] = {
            mkseg(pVF, NF, pB8, MM, pG + STRIDE * PP * MM, MM, NF,
                  STRIDE * PP, MM, pH1, MM),
        };
        launch_segs(s, 1);
    }

    // Parseval reduction (fp64, deterministic)
    reduceA_kernel<<<128, 128>>>(DFre, DFim);
    reduceB_kernel<<<1, 128>>>(d_out);
}